// round 12
// baseline (speedup 1.0000x reference)
#include <cuda_runtime.h>
#include <math.h>

#define BB 8
#define NN 16384
#define MM 128
#define CC 81
#define KPOS 128
#define NSAMP 256
#define BGCLS (CC - 1)
#define SEL_T 1024
#define LOSS_BX 32
#define NPART (LOSS_BX)

typedef unsigned int u32;
typedef unsigned short u16;

// ---------------- scratch ----------------
__device__ float g_miou[BB][NN];
__device__ int   g_match[BB][NN];
__device__ int   g_selidx[BB][NSAMP];
__device__ float g_part[BB][NPART][2];
__device__ unsigned g_ticket;

__device__ __forceinline__ u32 ford(float f) {
    u32 u = __float_as_uint(f);
    return (u & 0x80000000u) ? ~u : (u | 0x80000000u);
}

// ---------------- K1: IoU max/argmax, 2 preds/thread, 128-thr blocks ----------------
__global__ __launch_bounds__(128) void k_iou(const float* __restrict__ bp,
                                             const float* __restrict__ rt) {
    __shared__ float4 s_g[MM];
    __shared__ float  s_area[MM];
    int b = blockIdx.y;
    int tid = threadIdx.x;
    if (blockIdx.x == 0 && b == 0 && tid == 0) g_ticket = 0;
    {
        const float* v = rt + ((size_t)b * MM + tid) * 8;
        float x0 = v[0], y0 = v[1], x1 = v[2], y1 = v[3];
        float x2 = v[4], y2 = v[5], x3 = v[6], y3 = v[7];
        float mnx = fminf(fminf(x0, x1), fminf(x2, x3));
        float mny = fminf(fminf(y0, y1), fminf(y2, y3));
        float mxx = fmaxf(fmaxf(x0, x1), fmaxf(x2, x3));
        float mxy = fmaxf(fmaxf(y0, y1), fmaxf(y2, y3));
        s_g[tid] = make_float4(mnx, mny, mxx, mxy);
        s_area[tid] = (mxx - mnx) * (mxy - mny);
    }
    __syncthreads();

    int n0 = blockIdx.x * 256 + tid;
    int n1 = n0 + 128;

    float A_pmnx[2], A_pmxx[2], A_pmny[2], A_pmxy[2], A_area[2];
    #pragma unroll
    for (int q = 0; q < 2; q++) {
        int n = q ? n1 : n0;
        const float* p = bp + ((size_t)b * NN + n) * 5;
        float cx = p[0], cy = p[1], w = p[2], h = p[3], a = p[4];
        float c = cosf(a), s = sinf(a);
        float dx = w * 0.5f, dy = h * 0.5f;
        float xs0 = cx - dx * c + dy * s;
        float xs1 = cx + dx * c + dy * s;
        float xs2 = cx + dx * c - dy * s;
        float xs3 = cx - dx * c - dy * s;
        float ys0 = cy - dx * s - dy * c;
        float ys1 = cy + dx * s - dy * c;
        float ys2 = cy + dx * s + dy * c;
        float ys3 = cy - dx * s + dy * c;
        A_pmnx[q] = fminf(fminf(xs0, xs1), fminf(xs2, xs3));
        A_pmxx[q] = fmaxf(fmaxf(xs0, xs1), fmaxf(xs2, xs3));
        A_pmny[q] = fminf(fminf(ys0, ys1), fminf(ys2, ys3));
        A_pmxy[q] = fmaxf(fmaxf(ys0, ys1), fmaxf(ys2, ys3));
        A_area[q] = (A_pmxx[q] - A_pmnx[q]) * (A_pmxy[q] - A_pmny[q]);
    }

    float bi[2][2], bS[2][2];
    int bj[2][2];
    #pragma unroll
    for (int q = 0; q < 2; q++)
        #pragma unroll
        for (int cc2 = 0; cc2 < 2; cc2++) { bi[q][cc2] = -1.0f; bS[q][cc2] = 1.0f; bj[q][cc2] = cc2 * 64; }

    #pragma unroll
    for (int half = 0; half < 2; half++) {
        int base = half * 64;
        #pragma unroll 8
        for (int jj = 0; jj < 64; jj++) {
            int j = base + jj;
            float4 g = s_g[j];
            float sa = s_area[j];
            #pragma unroll
            for (int q = 0; q < 2; q++) {
                float iw = fmaxf(fminf(A_pmxx[q], g.z) - fmaxf(A_pmnx[q], g.x), 0.0f);
                float ih = fmaxf(fminf(A_pmxy[q], g.w) - fmaxf(A_pmny[q], g.y), 0.0f);
                float inter = iw * ih;
                float S = A_area[q] + sa;
                if (inter * bS[q][half] > bi[q][half] * S) {
                    bi[q][half] = inter; bS[q][half] = S; bj[q][half] = j;
                }
            }
        }
    }
    #pragma unroll
    for (int q = 0; q < 2; q++) {
        if (bi[q][1] * bS[q][0] > bi[q][0] * bS[q][1]) {
            bi[q][0] = bi[q][1]; bS[q][0] = bS[q][1]; bj[q][0] = bj[q][1];
        }
        float un = bS[q][0] - bi[q][0];
        float best = bi[q][0] / fmaxf(un, 1e-7f);   // reference rounding
        int n = q ? n1 : n0;
        g_miou[b][n] = best;
        g_match[b][n] = bj[q][0];
    }
}

// ---------------- scan helper: 2048 bins, find k-crossing bin ----------------
__device__ __forceinline__ void scan_pick(u32* hist, int k, int tid, int lane, int warp,
                                          int* s_w32, int* sh_digit, int* sh_below) {
    int h0 = (int)hist[2 * tid], h1 = (int)hist[2 * tid + 1];
    int sum2 = h0 + h1;
    int inc = sum2;
    #pragma unroll
    for (int o = 1; o < 32; o <<= 1) {
        int nv = __shfl_up_sync(~0u, inc, o);
        if (lane >= o) inc += nv;
    }
    if (lane == 31) s_w32[warp] = inc;
    __syncthreads();
    if (tid < 32) {
        int v = s_w32[lane];
        int e = v;
        #pragma unroll
        for (int o = 1; o < 32; o <<= 1) {
            int nv = __shfl_up_sync(~0u, e, o);
            if (lane >= o) e += nv;
        }
        s_w32[lane] = e - v;
    }
    __syncthreads();
    int excl = s_w32[warp] + inc - sum2;
    int c0 = excl + h0;
    int c1 = c0 + h1;
    if (c0 >= k && excl < k) { *sh_digit = 2 * tid;     *sh_below = excl; }
    if (c1 >= k && c0 < k)   { *sh_digit = 2 * tid + 1; *sh_below = c0; }
    __syncthreads();
}

// ---------------- K2: exact top-128 radix select v4 ----------------
extern __shared__ u32 sk32[];  // NN keys = 64KB dynamic
__global__ __launch_bounds__(SEL_T) void k_select() {
    __shared__ u32 hist[2048];       // reused as bm[512] + pc[512] in final phase
    __shared__ u16 cand[NN];         // 32KB
    __shared__ int s_w32[32];
    __shared__ int sh_digit, sh_below;
    __shared__ int s_nc, s_nonc;
    int b = blockIdx.x >> 1, kind = blockIdx.x & 1;
    int tid = threadIdx.x, lane = tid & 31, warp = tid >> 5;

    u32 C = (kind == 0) ? ~ford(-1.0f) : 0xFFFFFFFFu;   // duplicate-heavy constant key

    hist[tid] = 0; hist[tid + 1024] = 0;
    if (tid == 0) { s_nc = 0; s_nonc = 0; }
    __syncthreads();

    // build keys + pass-1 histogram (top 11 bits); constant key counted per-warp
    int ccnt = 0;
    #pragma unroll
    for (int r = 0; r < NN / SEL_T; r++) {
        int i = r * SEL_T + tid;
        float mi = g_miou[b][i];
        bool pos = (mi >= 0.5f);
        u32 key;
        if (kind == 0) { float score = pos ? mi : -1.0f; key = ~ford(score); }
        else           { key = pos ? 0xFFFFFFFFu : ford(mi); }
        sk32[i] = key;
        if (key == C) ccnt++;
        else atomicAdd(&hist[key >> 21], 1u);
    }
    #pragma unroll
    for (int o = 16; o; o >>= 1) ccnt += __shfl_xor_sync(~0u, ccnt, o);
    if (lane == 0 && ccnt) atomicAdd(&hist[C >> 21], (u32)ccnt);
    __syncthreads();

    int k = 128;
    scan_pick(hist, k, tid, lane, warp, s_w32, &sh_digit, &sh_below);
    u32 d1 = (u32)sh_digit;
    k -= sh_below;
    __syncthreads();

    // candidate compaction (warp-aggregated) + non-constant count
    #pragma unroll
    for (int r = 0; r < NN / SEL_T; r++) {
        int i = r * SEL_T + tid;
        u32 key = sk32[i];
        bool w = ((key >> 21) == d1);
        unsigned ball = __ballot_sync(~0u, w);
        if (ball) {
            int leader = __ffs(ball) - 1;
            int base = 0;
            if (lane == leader) base = atomicAdd(&s_nc, __popc(ball));
            base = __shfl_sync(~0u, base, leader);
            if (w) cand[base + __popc(ball & ((1u << lane) - 1u))] = (u16)i;
        }
        bool nz = w && (key != C);
        unsigned bz = __ballot_sync(~0u, nz);
        if (lane == 0 && bz) atomicAdd(&s_nonc, __popc(bz));
    }
    __syncthreads();
    int nc = s_nc;
    u32 t;
    if (s_nonc == 0) {
        // threshold bin is pure constant-key: threshold key is C, k unchanged
        t = C;
    } else {
        // pass 2: bits [10:21) over candidates
        hist[tid] = 0; hist[tid + 1024] = 0;
        __syncthreads();
        for (int ci = tid; ci < nc; ci += SEL_T)
            atomicAdd(&hist[(sk32[cand[ci]] >> 10) & 0x7FFu], 1u);
        __syncthreads();
        scan_pick(hist, k, tid, lane, warp, s_w32, &sh_digit, &sh_below);
        u32 d2 = (u32)sh_digit;
        k -= sh_below;
        __syncthreads();

        // pass 3: bits [0:10)
        hist[tid] = 0; hist[tid + 1024] = 0;
        __syncthreads();
        u32 pref2 = (d1 << 21) | (d2 << 10);
        for (int ci = tid; ci < nc; ci += SEL_T) {
            u32 key = sk32[cand[ci]];
            if ((key & 0xFFFFFC00u) == pref2) atomicAdd(&hist[key & 0x3FFu], 1u);
        }
        __syncthreads();
        scan_pick(hist, k, tid, lane, warp, s_w32, &sh_digit, &sh_below);
        u32 d3 = (u32)sh_digit;
        k -= sh_below;
        __syncthreads();
        t = pref2 | d3;
    }

    int below_total = 128 - k;      // slots for strict-below; k slots for equals

    // strict-below compaction (set semantics, deterministic slots)
    int c = 0;
    #pragma unroll
    for (int r = 0; r < NN / SEL_T; r++)
        if (sk32[r * SEL_T + tid] < t) c++;
    int inc = c;
    #pragma unroll
    for (int o = 1; o < 32; o <<= 1) {
        int nv = __shfl_up_sync(~0u, inc, o);
        if (lane >= o) inc += nv;
    }
    if (lane == 31) s_w32[warp] = inc;
    __syncthreads();
    if (tid == 0) {
        int run = 0;
        #pragma unroll
        for (int j = 0; j < 32; j++) { int tv = s_w32[j]; s_w32[j] = run; run += tv; }
    }
    __syncthreads();
    int off = s_w32[warp] + inc - c;
    #pragma unroll
    for (int r = 0; r < NN / SEL_T; r++) {
        int i = r * SEL_T + tid;
        if (sk32[i] < t) g_selidx[b][kind * 128 + off++] = i;
    }
    __syncthreads();   // done with s_w32; hist reuse begins

    // equals ranking via bitmask: word w covers indices [32w, 32w+32)
    u32* bm = hist;                  // [0..512)
    int* pc = (int*)(hist + 512);    // [512..1024)
    #pragma unroll
    for (int q = 0; q < 16; q++) {
        int i = q * 1024 + tid;      // warp covers 32 consecutive indices
        bool eq = (sk32[i] == t);
        u32 ball = __ballot_sync(~0u, eq);
        if (lane == 0) bm[q * 32 + warp] = ball;
    }
    __syncthreads();
    int v512 = 0, inc512 = 0;
    if (tid < 512) {
        v512 = __popc(bm[tid]);
        inc512 = v512;
        #pragma unroll
        for (int o = 1; o < 32; o <<= 1) {
            int nv = __shfl_up_sync(~0u, inc512, o);
            if (lane >= o) inc512 += nv;
        }
        if (lane == 31) s_w32[warp] = inc512;   // warps 0..15
    }
    __syncthreads();
    if (tid < 16) {
        int v = s_w32[tid];
        int e = v;
        #pragma unroll
        for (int o = 1; o < 16; o <<= 1) {
            int nv = __shfl_up_sync(0xFFFFu, e, o);
            if (tid >= o) e += nv;
        }
        s_w32[tid] = e - v;   // exclusive warp base
    }
    __syncthreads();
    if (tid < 512) pc[tid] = s_w32[tid >> 5] + inc512 - v512;   // exclusive word prefix
    __syncthreads();
    #pragma unroll
    for (int q = 0; q < 16; q++) {
        int i = q * 1024 + tid;
        bool eq = (sk32[i] == t);
        u32 ball = __ballot_sync(~0u, eq);
        if (eq) {
            int rank = pc[q * 32 + warp] + __popc(ball & ((1u << lane) - 1u));
            int pos = below_total + rank;
            if (pos < 128) g_selidx[b][kind * 128 + pos] = i;
        }
    }
}

// ---------------- K3: warp-per-sample loss + fused final combine ----------------
__global__ __launch_bounds__(256) void k_loss(const float* __restrict__ bp,
                                              const float* __restrict__ cp,
                                              const float* __restrict__ rt,
                                              const int* __restrict__ labels,
                                              float* __restrict__ out) {
    __shared__ float s_c[8], s_r[8];
    __shared__ float s_fc[256], s_fr[256];
    __shared__ bool s_last;
    int b = blockIdx.y;
    int w = threadIdx.x >> 5, lane = threadIdx.x & 31;
    int s = blockIdx.x * 8 + w;
    int idx = g_selidx[b][s];
    float miou = g_miou[b][idx];
    bool pos = (miou >= 0.5f);
    bool is_pos_slot = (s < KPOS);
    bool valid = is_pos_slot ? pos : (!pos);
    int m = g_match[b][idx];
    int tgt = pos ? labels[b * MM + m] : BGCLS;

    const float* lg = cp + ((size_t)b * NN + idx) * CC;
    float v0 = lg[lane];
    float v1 = (lane + 32 < CC) ? lg[lane + 32] : -INFINITY;
    float v2 = (lane + 64 < CC) ? lg[lane + 64] : -INFINITY;
    float mx = fmaxf(v0, fmaxf(v1, v2));
    #pragma unroll
    for (int o = 16; o; o >>= 1) mx = fmaxf(mx, __shfl_xor_sync(~0u, mx, o));
    float se = expf(v0 - mx);
    if (lane + 32 < CC) se += expf(v1 - mx);
    if (lane + 64 < CC) se += expf(v2 - mx);
    #pragma unroll
    for (int o = 16; o; o >>= 1) se += __shfl_xor_sync(~0u, se, o);

    if (lane == 0) {
        float nll = logf(se) + mx - __ldg(lg + tgt);
        s_c[w] = valid ? nll : 0.0f;
        float reg = 0.0f;
        if (is_pos_slot && valid) {
            const float* v = rt + ((size_t)b * MM + m) * 8;
            float x0 = v[0], y0 = v[1], x1 = v[2], y1 = v[3];
            float x2 = v[4], y2 = v[5], x3 = v[6], y3 = v[7];
            float e1x = x1 - x0, e1y = y1 - y0;
            float e2x = x3 - x0, e2y = y3 - y0;
            float gb[5];
            gb[0] = (x0 + x1 + x2 + x3) * 0.25f;
            gb[1] = (y0 + y1 + y2 + y3) * 0.25f;
            gb[2] = sqrtf(e1x * e1x + e1y * e1y);
            gb[3] = sqrtf(e2x * e2x + e2y * e2y);
            gb[4] = atan2f(e1y, e1x);
            const float* pb = bp + ((size_t)b * NN + idx) * 5;
            #pragma unroll
            for (int d = 0; d < 5; d++) {
                float ad = fabsf(pb[d] - gb[d]);
                reg += (ad < 1.0f) ? 0.5f * ad * ad : ad - 0.5f;
            }
        }
        s_r[w] = reg;
    }
    __syncthreads();
    if (threadIdx.x == 0) {
        float cv = 0.0f, rv = 0.0f;
        #pragma unroll
        for (int j = 0; j < 8; j++) { cv += s_c[j]; rv += s_r[j]; }
        g_part[b][blockIdx.x][0] = cv;
        g_part[b][blockIdx.x][1] = rv;
        __threadfence();
        unsigned done = atomicAdd(&g_ticket, 1u);
        s_last = (done == (unsigned)(BB * NPART - 1));
    }
    __syncthreads();
    if (s_last) {
        const float* gp = &g_part[0][0][0];
        int t = threadIdx.x;
        s_fc[t] = gp[2 * t];
        s_fr[t] = gp[2 * t + 1];
        __syncthreads();
        for (int st = 128; st > 0; st >>= 1) {
            if (t < st) { s_fc[t] += s_fc[t + st]; s_fr[t] += s_fr[t + st]; }
            __syncthreads();
        }
        if (t == 0) {
            float cs = s_fc[0] / (float)BB;
            float rs = s_fr[0] / (float)BB;
            out[0] = cs + rs;
            out[1] = cs;
            out[2] = rs;
        }
    }
}

// ---------------- launch ----------------
extern "C" void kernel_launch(void* const* d_in, const int* in_sizes, int n_in,
                              void* d_out, int out_size) {
    const float* box_pred   = (const float*)d_in[0];
    const float* class_pred = (const float*)d_in[1];
    const float* regr_tgt   = (const float*)d_in[2];
    const int*   cls_tgt    = (const int*)d_in[3];
    (void)in_sizes; (void)n_in; (void)out_size;

    cudaFuncSetAttribute(k_select, cudaFuncAttributeMaxDynamicSharedMemorySize,
                         NN * (int)sizeof(u32));

    k_iou<<<dim3(NN / 256, BB), 128>>>(box_pred, regr_tgt);
    k_select<<<2 * BB, SEL_T, NN * sizeof(u32)>>>();
    k_loss<<<dim3(LOSS_BX, BB), 256>>>(box_pred, class_pred, regr_tgt, cls_tgt,
                                       (float*)d_out);
}

// round 13
// speedup vs baseline: 1.0576x; 1.0576x over previous
#include <cuda_runtime.h>
#include <math.h>

#define BB 8
#define NN 16384
#define MM 128
#define CC 81
#define KPOS 128
#define NSAMP 256
#define BGCLS (CC - 1)
#define SEL_T 1024
#define LOSS_BX 32
#define NPART (LOSS_BX)

typedef unsigned int u32;
typedef unsigned short u16;

// ---------------- scratch ----------------
__device__ float g_miou[BB][NN];
__device__ int   g_match[BB][NN];
__device__ int   g_selidx[BB][NSAMP];
__device__ float g_part[BB][NPART][2];
__device__ unsigned g_ticket;

__device__ __forceinline__ u32 ford(float f) {
    u32 u = __float_as_uint(f);
    return (u & 0x80000000u) ? ~u : (u | 0x80000000u);
}

// ---------------- K1: IoU max/argmax (R7 best config: 256thr, 2 preds) ----------------
__global__ __launch_bounds__(256) void k_iou(const float* __restrict__ bp,
                                             const float* __restrict__ rt) {
    __shared__ float4 s_g[MM];
    __shared__ float  s_area[MM];
    int b = blockIdx.y;
    int tid = threadIdx.x;
    if (blockIdx.x == 0 && b == 0 && tid == 0) g_ticket = 0;
    if (tid < MM) {
        const float* v = rt + ((size_t)b * MM + tid) * 8;
        float x0 = v[0], y0 = v[1], x1 = v[2], y1 = v[3];
        float x2 = v[4], y2 = v[5], x3 = v[6], y3 = v[7];
        float mnx = fminf(fminf(x0, x1), fminf(x2, x3));
        float mny = fminf(fminf(y0, y1), fminf(y2, y3));
        float mxx = fmaxf(fmaxf(x0, x1), fmaxf(x2, x3));
        float mxy = fmaxf(fmaxf(y0, y1), fmaxf(y2, y3));
        s_g[tid] = make_float4(mnx, mny, mxx, mxy);
        s_area[tid] = (mxx - mnx) * (mxy - mny);
    }
    __syncthreads();

    int n0 = blockIdx.x * 512 + tid;
    int n1 = n0 + 256;

    float A_pmnx[2], A_pmxx[2], A_pmny[2], A_pmxy[2], A_area[2];
    #pragma unroll
    for (int q = 0; q < 2; q++) {
        int n = q ? n1 : n0;
        const float* p = bp + ((size_t)b * NN + n) * 5;
        float cx = p[0], cy = p[1], w = p[2], h = p[3], a = p[4];
        float c = cosf(a), s = sinf(a);
        float dx = w * 0.5f, dy = h * 0.5f;
        float xs0 = cx - dx * c + dy * s;
        float xs1 = cx + dx * c + dy * s;
        float xs2 = cx + dx * c - dy * s;
        float xs3 = cx - dx * c - dy * s;
        float ys0 = cy - dx * s - dy * c;
        float ys1 = cy + dx * s - dy * c;
        float ys2 = cy + dx * s + dy * c;
        float ys3 = cy - dx * s + dy * c;
        A_pmnx[q] = fminf(fminf(xs0, xs1), fminf(xs2, xs3));
        A_pmxx[q] = fmaxf(fmaxf(xs0, xs1), fmaxf(xs2, xs3));
        A_pmny[q] = fminf(fminf(ys0, ys1), fminf(ys2, ys3));
        A_pmxy[q] = fmaxf(fmaxf(ys0, ys1), fmaxf(ys2, ys3));
        A_area[q] = (A_pmxx[q] - A_pmnx[q]) * (A_pmxy[q] - A_pmny[q]);
    }

    float bi[2][2], bS[2][2];
    int bj[2][2];
    #pragma unroll
    for (int q = 0; q < 2; q++)
        #pragma unroll
        for (int cc2 = 0; cc2 < 2; cc2++) { bi[q][cc2] = -1.0f; bS[q][cc2] = 1.0f; bj[q][cc2] = cc2 * 64; }

    #pragma unroll
    for (int half = 0; half < 2; half++) {
        int base = half * 64;
        #pragma unroll 8
        for (int jj = 0; jj < 64; jj++) {
            int j = base + jj;
            float4 g = s_g[j];
            float sa = s_area[j];
            #pragma unroll
            for (int q = 0; q < 2; q++) {
                float iw = fmaxf(fminf(A_pmxx[q], g.z) - fmaxf(A_pmnx[q], g.x), 0.0f);
                float ih = fmaxf(fminf(A_pmxy[q], g.w) - fmaxf(A_pmny[q], g.y), 0.0f);
                float inter = iw * ih;
                float S = A_area[q] + sa;
                if (inter * bS[q][half] > bi[q][half] * S) {
                    bi[q][half] = inter; bS[q][half] = S; bj[q][half] = j;
                }
            }
        }
    }
    #pragma unroll
    for (int q = 0; q < 2; q++) {
        if (bi[q][1] * bS[q][0] > bi[q][0] * bS[q][1]) {
            bi[q][0] = bi[q][1]; bS[q][0] = bS[q][1]; bj[q][0] = bj[q][1];
        }
        float un = bS[q][0] - bi[q][0];
        float best = bi[q][0] / fmaxf(un, 1e-7f);   // reference rounding
        int n = q ? n1 : n0;
        g_miou[b][n] = best;
        g_match[b][n] = bj[q][0];
    }
}

// ---------------- scan helper: 2048 bins, find k-crossing bin ----------------
__device__ __forceinline__ void scan_pick(u32* hist, int k, int tid, int lane, int warp,
                                          int* s_w32, int* sh_digit, int* sh_below) {
    int h0 = (int)hist[2 * tid], h1 = (int)hist[2 * tid + 1];
    int sum2 = h0 + h1;
    int inc = sum2;
    #pragma unroll
    for (int o = 1; o < 32; o <<= 1) {
        int nv = __shfl_up_sync(~0u, inc, o);
        if (lane >= o) inc += nv;
    }
    if (lane == 31) s_w32[warp] = inc;
    __syncthreads();
    if (tid < 32) {
        int v = s_w32[lane];
        int e = v;
        #pragma unroll
        for (int o = 1; o < 32; o <<= 1) {
            int nv = __shfl_up_sync(~0u, e, o);
            if (lane >= o) e += nv;
        }
        s_w32[lane] = e - v;
    }
    __syncthreads();
    int excl = s_w32[warp] + inc - sum2;
    int c0 = excl + h0;
    int c1 = c0 + h1;
    if (c0 >= k && excl < k) { *sh_digit = 2 * tid;     *sh_below = excl; }
    if (c1 >= k && c0 < k)   { *sh_digit = 2 * tid + 1; *sh_below = c0; }
    __syncthreads();
}

// ---------------- K2: exact top-128 radix select v5 ----------------
extern __shared__ u32 sk32[];  // NN keys = 64KB dynamic
__global__ __launch_bounds__(SEL_T) void k_select() {
    __shared__ u32 hist[2048];
    __shared__ u16 cand[NN];          // general-path only
    __shared__ u32 bmB[512], bmE[512];
    __shared__ int s_w32[32];
    __shared__ int s_sums[32];
    __shared__ int sh_digit, sh_below;
    __shared__ int s_nc, s_ccnt, s_zcnt;
    int b = blockIdx.x >> 1, kind = blockIdx.x & 1;
    int tid = threadIdx.x, lane = tid & 31, warp = tid >> 5;

    // two duplicate-heavy constant keys
    u32 C = (kind == 0) ? ~ford(-1.0f) : 0xFFFFFFFFu;    // pos: score -1; neg: positives
    u32 Z = (kind == 0) ? C : ford(0.0f);                // neg: exact-zero miou class

    hist[tid] = 0; hist[tid + 1024] = 0;
    if (tid == 0) { s_nc = 0; s_ccnt = 0; s_zcnt = 0; }
    __syncthreads();

    // build keys + pass-1 histogram (top 11 bits); constants aggregated per-warp
    int ccnt = 0, zcnt = 0;
    #pragma unroll
    for (int r = 0; r < NN / SEL_T; r++) {
        int i = r * SEL_T + tid;
        float mi = g_miou[b][i];
        bool pos = (mi >= 0.5f);
        u32 key;
        if (kind == 0) { float score = pos ? mi : -1.0f; key = ~ford(score); }
        else           { key = pos ? 0xFFFFFFFFu : ford(mi); }
        sk32[i] = key;
        if (key == C) ccnt++;
        else if (key == Z) zcnt++;
        else atomicAdd(&hist[key >> 21], 1u);
    }
    #pragma unroll
    for (int o = 16; o; o >>= 1) {
        ccnt += __shfl_xor_sync(~0u, ccnt, o);
        zcnt += __shfl_xor_sync(~0u, zcnt, o);
    }
    if (lane == 0) {
        if (ccnt) { atomicAdd(&hist[C >> 21], (u32)ccnt); atomicAdd((u32*)&s_ccnt, (u32)ccnt); }
        if (zcnt) { atomicAdd(&hist[Z >> 21], (u32)zcnt); atomicAdd((u32*)&s_zcnt, (u32)zcnt); }
    }
    __syncthreads();

    int k = 128;
    scan_pick(hist, k, tid, lane, warp, s_w32, &sh_digit, &sh_below);
    u32 d1 = (u32)sh_digit;
    k -= sh_below;
    __syncthreads();

    // pure-constant-bin fast path (common): threshold key known immediately
    int nonP = -1;
    u32 P = 0;
    if (d1 == (C >> 21))      { P = C; nonP = (int)hist[d1] - s_ccnt; }
    else if (d1 == (Z >> 21)) { P = Z; nonP = (int)hist[d1] - s_zcnt; }

    u32 t;
    if (nonP == 0) {
        t = P;
    } else {
        // general path: compact candidates of bin d1, radix passes 2-3
        #pragma unroll
        for (int r = 0; r < NN / SEL_T; r++) {
            int i = r * SEL_T + tid;
            u32 key = sk32[i];
            bool w = ((key >> 21) == d1);
            unsigned ball = __ballot_sync(~0u, w);
            if (ball) {
                int leader = __ffs(ball) - 1;
                int base = 0;
                if (lane == leader) base = atomicAdd(&s_nc, __popc(ball));
                base = __shfl_sync(~0u, base, leader);
                if (w) cand[base + __popc(ball & ((1u << lane) - 1u))] = (u16)i;
            }
        }
        __syncthreads();
        int nc = s_nc;

        hist[tid] = 0; hist[tid + 1024] = 0;
        __syncthreads();
        for (int ci = tid; ci < nc; ci += SEL_T)
            atomicAdd(&hist[(sk32[cand[ci]] >> 10) & 0x7FFu], 1u);
        __syncthreads();
        scan_pick(hist, k, tid, lane, warp, s_w32, &sh_digit, &sh_below);
        u32 d2 = (u32)sh_digit;
        k -= sh_below;
        __syncthreads();

        hist[tid] = 0; hist[tid + 1024] = 0;
        __syncthreads();
        u32 pref2 = (d1 << 21) | (d2 << 10);
        for (int ci = tid; ci < nc; ci += SEL_T) {
            u32 key = sk32[cand[ci]];
            if ((key & 0xFFFFFC00u) == pref2) atomicAdd(&hist[key & 0x3FFu], 1u);
        }
        __syncthreads();
        scan_pick(hist, k, tid, lane, warp, s_w32, &sh_digit, &sh_below);
        u32 d3 = (u32)sh_digit;
        k -= sh_below;
        __syncthreads();
        t = pref2 | d3;
    }

    int below_total = 128 - k;

    // one sweep: build below + equals bitmasks (index order)
    #pragma unroll
    for (int r = 0; r < NN / SEL_T; r++) {
        int i = r * SEL_T + tid;
        u32 key = sk32[i];
        u32 ballB = __ballot_sync(~0u, key < t);
        u32 ballE = __ballot_sync(~0u, key == t);
        if (lane == 0) { bmB[r * 32 + warp] = ballB; bmE[r * 32 + warp] = ballE; }
    }
    __syncthreads();

    // dual exclusive scan: threads [0,512) own below-words, [512,1024) equal-words
    bool isE = (tid >= 512);
    int w = tid & 511;
    u32 word = isE ? bmE[w] : bmB[w];
    int v = __popc(word);
    int inc = v;
    #pragma unroll
    for (int o = 1; o < 32; o <<= 1) {
        int nv = __shfl_up_sync(~0u, inc, o);
        if (lane >= o) inc += nv;
    }
    if (lane == 31) s_sums[warp] = inc;   // warps 0-15: B, 16-31: E
    __syncthreads();
    if (tid < 32) {
        int vv = s_sums[tid];
        int e = vv;
        #pragma unroll
        for (int o = 1; o < 16; o <<= 1) {   // segmented at 16 (two independent halves)
            int nv = __shfl_up_sync(~0u, e, o);
            if ((tid & 15) >= o) e += nv;
        }
        s_sums[tid] = e - vv;
    }
    __syncthreads();
    int pc = s_sums[warp] + inc - v;       // exclusive word prefix within its half

    // owning thread emits its word's indices
    int sel_base = kind * 128;
    if (!isE) {
        int basep = pc;                     // below_total <= 127, all emitted
        u32 wd = word;
        while (wd) {
            int bit = __ffs(wd) - 1; wd &= wd - 1;
            g_selidx[b][sel_base + basep++] = w * 32 + bit;
        }
    } else {
        int start = below_total + pc;
        if (start < 128) {
            u32 wd = word;
            while (wd && start < 128) {
                int bit = __ffs(wd) - 1; wd &= wd - 1;
                g_selidx[b][sel_base + start++] = w * 32 + bit;
            }
        }
    }
}

// ---------------- K3: warp-per-sample loss + fused final combine ----------------
__global__ __launch_bounds__(256) void k_loss(const float* __restrict__ bp,
                                              const float* __restrict__ cp,
                                              const float* __restrict__ rt,
                                              const int* __restrict__ labels,
                                              float* __restrict__ out) {
    __shared__ float s_c[8], s_r[8];
    __shared__ float s_fc[256], s_fr[256];
    __shared__ bool s_last;
    int b = blockIdx.y;
    int w = threadIdx.x >> 5, lane = threadIdx.x & 31;
    int s = blockIdx.x * 8 + w;
    int idx = g_selidx[b][s];
    float miou = g_miou[b][idx];
    bool pos = (miou >= 0.5f);
    bool is_pos_slot = (s < KPOS);
    bool valid = is_pos_slot ? pos : (!pos);
    int m = g_match[b][idx];
    int tgt = pos ? labels[b * MM + m] : BGCLS;

    const float* lg = cp + ((size_t)b * NN + idx) * CC;
    float v0 = lg[lane];
    float v1 = (lane + 32 < CC) ? lg[lane + 32] : -INFINITY;
    float v2 = (lane + 64 < CC) ? lg[lane + 64] : -INFINITY;
    float mx = fmaxf(v0, fmaxf(v1, v2));
    #pragma unroll
    for (int o = 16; o; o >>= 1) mx = fmaxf(mx, __shfl_xor_sync(~0u, mx, o));
    float se = expf(v0 - mx);
    if (lane + 32 < CC) se += expf(v1 - mx);
    if (lane + 64 < CC) se += expf(v2 - mx);
    #pragma unroll
    for (int o = 16; o; o >>= 1) se += __shfl_xor_sync(~0u, se, o);

    if (lane == 0) {
        float nll = logf(se) + mx - __ldg(lg + tgt);
        s_c[w] = valid ? nll : 0.0f;
        float reg = 0.0f;
        if (is_pos_slot && valid) {
            const float* v = rt + ((size_t)b * MM + m) * 8;
            float x0 = v[0], y0 = v[1], x1 = v[2], y1 = v[3];
            float x2 = v[4], y2 = v[5], x3 = v[6], y3 = v[7];
            float e1x = x1 - x0, e1y = y1 - y0;
            float e2x = x3 - x0, e2y = y3 - y0;
            float gb[5];
            gb[0] = (x0 + x1 + x2 + x3) * 0.25f;
            gb[1] = (y0 + y1 + y2 + y3) * 0.25f;
            gb[2] = sqrtf(e1x * e1x + e1y * e1y);
            gb[3] = sqrtf(e2x * e2x + e2y * e2y);
            gb[4] = atan2f(e1y, e1x);
            const float* pb = bp + ((size_t)b * NN + idx) * 5;
            #pragma unroll
            for (int d = 0; d < 5; d++) {
                float ad = fabsf(pb[d] - gb[d]);
                reg += (ad < 1.0f) ? 0.5f * ad * ad : ad - 0.5f;
            }
        }
        s_r[w] = reg;
    }
    __syncthreads();
    if (threadIdx.x == 0) {
        float cv = 0.0f, rv = 0.0f;
        #pragma unroll
        for (int j = 0; j < 8; j++) { cv += s_c[j]; rv += s_r[j]; }
        g_part[b][blockIdx.x][0] = cv;
        g_part[b][blockIdx.x][1] = rv;
        __threadfence();
        unsigned done = atomicAdd(&g_ticket, 1u);
        s_last = (done == (unsigned)(BB * NPART - 1));
    }
    __syncthreads();
    if (s_last) {
        const float* gp = &g_part[0][0][0];
        int t = threadIdx.x;
        s_fc[t] = gp[2 * t];
        s_fr[t] = gp[2 * t + 1];
        __syncthreads();
        for (int st = 128; st > 0; st >>= 1) {
            if (t < st) { s_fc[t] += s_fc[t + st]; s_fr[t] += s_fr[t + st]; }
            __syncthreads();
        }
        if (t == 0) {
            float cs = s_fc[0] / (float)BB;
            float rs = s_fr[0] / (float)BB;
            out[0] = cs + rs;
            out[1] = cs;
            out[2] = rs;
        }
    }
}

// ---------------- launch ----------------
extern "C" void kernel_launch(void* const* d_in, const int* in_sizes, int n_in,
                              void* d_out, int out_size) {
    const float* box_pred   = (const float*)d_in[0];
    const float* class_pred = (const float*)d_in[1];
    const float* regr_tgt   = (const float*)d_in[2];
    const int*   cls_tgt    = (const int*)d_in[3];
    (void)in_sizes; (void)n_in; (void)out_size;

    cudaFuncSetAttribute(k_select, cudaFuncAttributeMaxDynamicSharedMemorySize,
                         NN * (int)sizeof(u32));

    k_iou<<<dim3(NN / 512, BB), 256>>>(box_pred, regr_tgt);
    k_select<<<2 * BB, SEL_T, NN * sizeof(u32)>>>();
    k_loss<<<dim3(LOSS_BX, BB), 256>>>(box_pred, class_pred, regr_tgt, cls_tgt,
                                       (float*)d_out);
}